// round 17
// baseline (speedup 1.0000x reference)
#include <cuda_runtime.h>
#include <cuda_bf16.h>
#include <cuda_fp16.h>

// Problem constants (fixed shapes for this problem)
#define NN 50000
#define EE 800000
#define DD 128
#define HH 32

// -------- scratch (no allocations allowed) --------
// Self-cleaning invariant: g_aggh, g_deg, g_agg2 are zero before every call.
// (Static zero-init covers the first call; epi/final re-zero after reading.)
__device__ __align__(16) __half2 g_y1h[NN * 16]; // x @ W1_l^T packed fp16x2
__device__ __align__(16) float  g_z1[NN * HH];   // x @ W1_r^T (fp32)
__device__ __align__(16) __half2 g_aggh[NN * 16];// scatter-sum of y1 (fp16x2)
__device__ __align__(16) float  g_deg[NN];
__device__ __align__(16) float  g_sl[NN];        // h @ W2_l^T
__device__ __align__(16) float  g_sr[NN];        // h @ W2_r^T
__device__ __align__(16) float  g_agg2[NN];      // scatter-sum of s_l
__device__ int   g_is64;                         // edge_index dtype flag

// load node index (always < 2^31) as 32-bit regardless of storage width
__device__ __forceinline__ int edge_at32(const void* ei, long long pos, int is64) {
    return is64 ? ((const int*)ei)[2 * pos] : ((const int*)ei)[pos];
}

// -------- tf32 helpers --------
__device__ __forceinline__ float f2tf32f(float f) {
    unsigned u;
    asm("cvt.rna.tf32.f32 %0, %1;" : "=r"(u) : "f"(f));
    return __uint_as_float(u);
}
__device__ __forceinline__ void mma_tf32(float* d, unsigned a0, unsigned a1,
                                         unsigned a2, unsigned a3,
                                         unsigned b0, unsigned b1) {
    asm volatile(
        "mma.sync.aligned.m16n8k8.row.col.f32.tf32.tf32.f32 "
        "{%0,%1,%2,%3}, {%4,%5,%6,%7}, {%8,%9}, {%0,%1,%2,%3};\n"
        : "+f"(d[0]), "+f"(d[1]), "+f"(d[2]), "+f"(d[3])
        : "r"(a0), "r"(a1), "r"(a2), "r"(a3), "r"(b0), "r"(b1));
}

// Dynamic smem layout: xs[64][132] then wt[128][72]
#define XS_STRIDE 132
#define WT_STRIDE 72
#define XS_ELEMS  (64 * XS_STRIDE)
#define WT_ELEMS  (128 * WT_STRIDE)
#define LIN1_SMEM_BYTES ((XS_ELEMS + WT_ELEMS) * (int)sizeof(float))

// -------- fused: dtype detect + deg histogram + tf32 MMA linear --------------
// deg depends only on the edge list, so its 800k REDs overlap the tensor work
// here instead of loading scatter1's critical path.
__global__ __launch_bounds__(128) void lin1_mma_kernel(
    const float* __restrict__ x,
    const float* __restrict__ W1l,
    const float* __restrict__ W1r,
    const unsigned* __restrict__ ei_words,
    const void* __restrict__ ei,
    long long E,
    int n)
{
    extern __shared__ float smem[];
    float (*xs)[XS_STRIDE] = (float (*)[XS_STRIDE])smem;              // 64 x 132
    float (*wt)[WT_STRIDE] = (float (*)[WT_STRIDE])(smem + XS_ELEMS); // 128 x 72

    int tid = threadIdx.x;
    int node0 = blockIdx.x * 64;

    // ---- per-block dtype detect (all blocks; barrier included) ----
    unsigned w = ei_words[2 * tid + 1];  // high words if int64
    int is64 = __syncthreads_and(w == 0u) ? 1 : 0;
    if (blockIdx.x == 0 && tid == 0) g_is64 = is64;

    // ---- deg histogram (fire-and-forget REDs overlap MMA below) ----
    {
        long long stride = (long long)gridDim.x * 128;
        for (long long e = (long long)blockIdx.x * 128 + tid; e < E; e += stride) {
            int d = edge_at32(ei, E + e, is64);
            atomicAdd(&g_deg[d], 1.0f);
        }
    }

    // ---- weight + x tiles (rounded to tf32 in smem) ----
    for (int idx = tid; idx < DD * 64; idx += 128) {
        int k = idx & 127, j = idx >> 7;
        float wv = (j < HH) ? W1l[j * DD + k] : W1r[(j - HH) * DD + k];
        wt[k][j] = f2tf32f(wv);
    }
    for (int idx = tid; idx < 64 * (DD / 4); idx += 128) {
        int r = idx >> 5, c4 = idx & 31;
        float4 v = (node0 + r < n)
                 ? ((const float4*)(x + (size_t)(node0 + r) * DD))[c4]
                 : make_float4(0.f, 0.f, 0.f, 0.f);
        v.x = f2tf32f(v.x); v.y = f2tf32f(v.y);
        v.z = f2tf32f(v.z); v.w = f2tf32f(v.w);
        *(float4*)&xs[r][c4 * 4] = v;
    }
    __syncthreads();

    int warp = tid >> 5, lane = tid & 31;
    int g = lane >> 2, tig = lane & 3;
    int m0 = warp * 16;

    float acc[8][4];
#pragma unroll
    for (int nt = 0; nt < 8; nt++)
#pragma unroll
        for (int c = 0; c < 4; c++) acc[nt][c] = 0.0f;

#pragma unroll
    for (int kc = 0; kc < 16; kc++) {
        int k0 = kc * 8;
        unsigned a0 = __float_as_uint(xs[m0 + g][k0 + tig]);
        unsigned a1 = __float_as_uint(xs[m0 + g + 8][k0 + tig]);
        unsigned a2 = __float_as_uint(xs[m0 + g][k0 + tig + 4]);
        unsigned a3 = __float_as_uint(xs[m0 + g + 8][k0 + tig + 4]);

#pragma unroll
        for (int nt = 0; nt < 8; nt++) {
            unsigned b0 = __float_as_uint(wt[k0 + tig][nt * 8 + g]);
            unsigned b1 = __float_as_uint(wt[k0 + tig + 4][nt * 8 + g]);
            mma_tf32(acc[nt], a0, a1, a2, a3, b0, b1);
        }
    }

    int node_a = node0 + m0 + g;
    int node_b = node_a + 8;
#pragma unroll
    for (int nt = 0; nt < 8; nt++) {
        int j = nt * 8 + 2 * tig;       // even output column
        if (j < HH) {
            // y1 -> packed half2
            if (node_a < n) g_y1h[node_a * 16 + (j >> 1)] = __floats2half2_rn(acc[nt][0], acc[nt][1]);
            if (node_b < n) g_y1h[node_b * 16 + (j >> 1)] = __floats2half2_rn(acc[nt][2], acc[nt][3]);
        } else {
            int jj = j & 31;
            if (node_a < n) *(float2*)&g_z1[node_a * HH + jj] = make_float2(acc[nt][0], acc[nt][1]);
            if (node_b < n) *(float2*)&g_z1[node_b * HH + jj] = make_float2(acc[nt][2], acc[nt][3]);
        }
    }
}

// -------- layer-1 edge scatter: 4 lanes/edge, 16B vector fp16 REDs only -----
__global__ __launch_bounds__(256) void scatter1_kernel(const void* __restrict__ ei, long long E) {
    long long t = (long long)blockIdx.x * blockDim.x + threadIdx.x;
    long long e = t >> 2;
    int sub = (int)(t & 3);              // 8-feature chunk (16B)
    if (e >= E) return;
    int is64 = g_is64;
    int s = edge_at32(ei, e, is64);
    int d = edge_at32(ei, E + e, is64);
    uint4 v = *(const uint4*)&g_y1h[(size_t)s * 16 + sub * 4];
    __half2* dstp = &g_aggh[(size_t)d * 16 + sub * 4];
    asm volatile(
        "red.global.add.noftz.v4.f16x2 [%0], {%1, %2, %3, %4};"
        :: "l"(dstp), "r"(v.x), "r"(v.y), "r"(v.z), "r"(v.w)
        : "memory");
}

// -------- layer-1 epilogue + layer-2 linear: 8 threads/node ------------------
// Reads agg row then zeroes it (self-cleaning for the next replay).
__global__ __launch_bounds__(256) void epi_kernel(
    const float* __restrict__ b1,
    const float* __restrict__ W2l,
    const float* __restrict__ W2r,
    int n)
{
    __shared__ float sb1[HH], swl[HH], swr[HH];
    int t = blockIdx.x * blockDim.x + threadIdx.x;
    int node = t >> 3;         // 8 threads per node
    int q = t & 7;             // 4-feature slice (2 half2)
    bool valid = (node < n);
    int nd = valid ? node : (n - 1);   // clamp (keep full warp for shfl)

    // issue global loads first (independent of smem weights)
    uint2 av = *(const uint2*)&g_aggh[(size_t)nd * 16 + q * 2];
    float4 z = *(const float4*)&g_z1[(size_t)nd * HH + q * 4];
    float dg = g_deg[nd];

    if (threadIdx.x < HH) {
        sb1[threadIdx.x] = b1[threadIdx.x];
        swl[threadIdx.x] = W2l[threadIdx.x];
        swr[threadIdx.x] = W2r[threadIdx.x];
    }
    __syncthreads();

    // self-clean: zero this thread's slice of the agg row (owner only)
    if (valid) *(uint2*)&g_aggh[(size_t)node * 16 + q * 2] = make_uint2(0u, 0u);

    float2 a01 = __half22float2(*(__half2*)&av.x);
    float2 a23 = __half22float2(*(__half2*)&av.y);
    float rdeg = 1.0f / fmaxf(dg, 1.0f);
    int k = q * 4;
    float h0 = fmaxf(fmaf(a01.x, rdeg, sb1[k + 0] + z.x), 0.0f);
    float h1 = fmaxf(fmaf(a01.y, rdeg, sb1[k + 1] + z.y), 0.0f);
    float h2 = fmaxf(fmaf(a23.x, rdeg, sb1[k + 2] + z.z), 0.0f);
    float h3 = fmaxf(fmaf(a23.y, rdeg, sb1[k + 3] + z.w), 0.0f);
    float sl = h0 * swl[k + 0] + h1 * swl[k + 1] + h2 * swl[k + 2] + h3 * swl[k + 3];
    float sr = h0 * swr[k + 0] + h1 * swr[k + 1] + h2 * swr[k + 2] + h3 * swr[k + 3];
    sl += __shfl_xor_sync(0xFFFFFFFFu, sl, 1);
    sr += __shfl_xor_sync(0xFFFFFFFFu, sr, 1);
    sl += __shfl_xor_sync(0xFFFFFFFFu, sl, 2);
    sr += __shfl_xor_sync(0xFFFFFFFFu, sr, 2);
    sl += __shfl_xor_sync(0xFFFFFFFFu, sl, 4);
    sr += __shfl_xor_sync(0xFFFFFFFFu, sr, 4);
    if (valid && q == 0) { g_sl[node] = sl; g_sr[node] = sr; }
}

// -------- layer-2 edge scatter: 1 edge/thread --------------------------------
__global__ __launch_bounds__(256) void scatter2_kernel(const void* __restrict__ ei, long long E) {
    long long e = (long long)blockIdx.x * blockDim.x + threadIdx.x;
    if (e >= E) return;
    int is64 = g_is64;
    int s = edge_at32(ei, e, is64);
    int d = edge_at32(ei, E + e, is64);
    atomicAdd(&g_agg2[d], g_sl[s]);
}

// -------- final: sigmoid(agg2/deg + b2 + s_r); self-cleans deg/agg2 ----------
__global__ __launch_bounds__(256) void final_kernel(const float* __restrict__ b2,
                                                    float* __restrict__ out, int n) {
    int i = blockIdx.x * blockDim.x + threadIdx.x;
    if (i >= n) return;
    float dg = g_deg[i];
    float a2 = g_agg2[i];
    float rdeg = 1.0f / fmaxf(dg, 1.0f);
    float v = fmaf(a2, rdeg, b2[0] + g_sr[i]);
    out[i] = 1.0f / (1.0f + expf(-v));
    g_deg[i] = 0.0f;     // self-clean for next replay
    g_agg2[i] = 0.0f;
}

extern "C" void kernel_launch(void* const* d_in, const int* in_sizes, int n_in,
                              void* d_out, int out_size) {
    const float* x   = (const float*)d_in[0];
    const void*  ei  = d_in[1];
    const float* W1l = (const float*)d_in[2];
    const float* b1  = (const float*)d_in[3];
    const float* W1r = (const float*)d_in[4];
    const float* W2l = (const float*)d_in[5];
    const float* b2  = (const float*)d_in[6];
    const float* W2r = (const float*)d_in[7];
    float* out = (float*)d_out;

    int n = in_sizes[0] / DD;            // 50000
    long long E = in_sizes[1] / 2;       // 800000

    cudaFuncSetAttribute(lin1_mma_kernel,
                         cudaFuncAttributeMaxDynamicSharedMemorySize,
                         LIN1_SMEM_BYTES);

    lin1_mma_kernel<<<(n + 63) / 64, 128, LIN1_SMEM_BYTES>>>(
        x, W1l, W1r, (const unsigned*)ei, ei, E, n);
    {
        long long threads = E * 4;       // 4 lanes per edge
        scatter1_kernel<<<(unsigned)((threads + 255) / 256), 256>>>(ei, E);
    }
    epi_kernel<<<(n * 8 + 255) / 256, 256>>>(b1, W2l, W2r, n);
    scatter2_kernel<<<(unsigned)((E + 255) / 256), 256>>>(ei, E);
    final_kernel<<<(n + 255) / 256, 256>>>(b2, out, n);
}